// round 6
// baseline (speedup 1.0000x reference)
#include <cuda_runtime.h>

#define NN 100000
#define L1_BLOCKS 148   // grid-stride layer1; one reduction per block

// ---- scratch (static __device__ globals; no allocation) ----
__device__ int    g_deg[NN];            // zero at load; node_prep resets to 0 each run
__device__ float  g_dinv[NN];
__device__ float4 g_S[NN];              // layer-1 accumulator (w lane = junk accumulate)
__device__ float4 g_Q[NN];              // {sx.xyz, w-accum}
__device__ float  g_part[L1_BLOCKS][16];// per-block layer-2 partials

// ---------------------------------------------------------------------------
// degree histogram over dst (self-loop added in node_prep); 2 edges/thread
__global__ void k_hist(const int* __restrict__ dst, int E) {
    int i      = blockIdx.x * blockDim.x + threadIdx.x;
    int stride = gridDim.x * blockDim.x;
    for (int e = i; e < E; e += stride) {
        atomicAdd(&g_deg[dst[e]], 1);
    }
}

// per-node: dinv = rsqrt(deg+1); Q = {dinv*x, dinv}; S = 0; reset deg for replay
__global__ void k_node_prep(const float* __restrict__ x) {
    int v = blockIdx.x * blockDim.x + threadIdx.x;
    if (v >= NN) return;
    float d = rsqrtf((float)(g_deg[v] + 1));
    g_deg[v]  = 0;                       // deterministic across graph replays
    g_dinv[v] = d;
    g_S[v] = make_float4(0.f, 0.f, 0.f, 0.f);
    g_Q[v] = make_float4(d * x[3 * v + 0], d * x[3 * v + 1], d * x[3 * v + 2], d);
}

// fused edge pass, 4 divergent lanes per edge, 2 edges per thread for MLP:
//   gather Q[s], gather dinv[d], red.v4 S[d] += Q[s], red Q[s].w += dinv[d]
__global__ void k_scatter(const int* __restrict__ src,
                          const int* __restrict__ dst, int E) {
    int i      = blockIdx.x * blockDim.x + threadIdx.x;
    int stride = gridDim.x * blockDim.x;
    for (int e = i; e < E; e += 2 * stride) {
        int e2 = e + stride;
        int s0 = src[e];
        int d0 = dst[e];
        int s1 = (e2 < E) ? src[e2] : s0;
        int d1 = (e2 < E) ? dst[e2] : d0;

        float4 q0 = g_Q[s0];
        float4 q1 = g_Q[s1];
        float dd0 = g_dinv[d0];
        float dd1 = g_dinv[d1];

        asm volatile("red.global.add.v4.f32 [%0], {%1,%2,%3,%4};"
                     :: "l"(&g_S[d0]), "f"(q0.x), "f"(q0.y), "f"(q0.z), "f"(q0.w)
                     : "memory");
        asm volatile("red.global.add.f32 [%0], %1;"
                     :: "l"(&((float*)&g_Q[s0])[3]), "f"(dd0)
                     : "memory");
        if (e2 < E) {
            asm volatile("red.global.add.v4.f32 [%0], {%1,%2,%3,%4};"
                         :: "l"(&g_S[d1]), "f"(q1.x), "f"(q1.y), "f"(q1.z), "f"(q1.w)
                         : "memory");
            asm volatile("red.global.add.f32 [%0], %1;"
                         :: "l"(&((float*)&g_Q[s1])[3]), "f"(dd1)
                         : "memory");
        }
    }
}

// layer-1 + layer-2 accumulation, grid-stride, ONE reduction per block:
//   a = dinv*(S + sx);  h1 = relu(a @ W1 + b1);  acc += (w*dinv)*h1
__global__ void __launch_bounds__(256) k_layer1(const float* __restrict__ W1,
                                                const float* __restrict__ b1) {
    float acc[16];
    #pragma unroll
    for (int j = 0; j < 16; j++) acc[j] = 0.f;

    // weights to registers once (uniform across threads, L1-const fast path)
    float w1r[48], b1r[16];
    #pragma unroll
    for (int j = 0; j < 16; j++) b1r[j] = __ldg(&b1[j]);
    #pragma unroll
    for (int j = 0; j < 48; j++) w1r[j] = __ldg(&W1[j]);

    int stride = gridDim.x * blockDim.x;
    for (int v = blockIdx.x * blockDim.x + threadIdx.x; v < NN; v += stride) {
        float4 S = g_S[v];
        float4 Q = g_Q[v];
        float  d = g_dinv[v];
        float  wv = Q.w * d;
        float a0 = d * (S.x + Q.x);
        float a1 = d * (S.y + Q.y);
        float a2 = d * (S.z + Q.z);
        #pragma unroll
        for (int j = 0; j < 16; j++) {
            float h = b1r[j] + a0 * w1r[j] + a1 * w1r[16 + j] + a2 * w1r[32 + j];
            acc[j] += wv * fmaxf(h, 0.f);
        }
    }

    // warp reduce 16 floats
    #pragma unroll
    for (int j = 0; j < 16; j++) {
        #pragma unroll
        for (int o = 16; o > 0; o >>= 1)
            acc[j] += __shfl_down_sync(0xffffffffu, acc[j], o);
    }
    __shared__ float sm[8][16];
    int lane = threadIdx.x & 31, w = threadIdx.x >> 5;
    if (lane == 0) {
        #pragma unroll
        for (int j = 0; j < 16; j++) sm[w][j] = acc[j];
    }
    __syncthreads();
    if (threadIdx.x < 16) {
        float s = 0.f;
        #pragma unroll
        for (int ww = 0; ww < 8; ww++) s += sm[ww][threadIdx.x];
        g_part[blockIdx.x][threadIdx.x] = s;     // plain store
    }
}

// reduce partials; out[j] = (sum16/N) @ W2 + b2
__global__ void k_final(const float* __restrict__ W2, const float* __restrict__ b2,
                        float* __restrict__ out) {
    __shared__ float red[16][16];
    __shared__ float sum16[16];
    int tid = threadIdx.x;          // 256 threads
    int j = tid & 15;               // column
    int g = tid >> 4;               // group 0..15
    float s = 0.f;
    for (int b = g; b < L1_BLOCKS; b += 16)
        s += g_part[b][j];
    red[g][j] = s;
    __syncthreads();
    if (tid < 16) {
        float t = 0.f;
        #pragma unroll
        for (int gg = 0; gg < 16; gg++) t += red[gg][tid];
        sum16[tid] = t * (1.0f / (float)NN);
    }
    __syncthreads();
    if (tid < 32) {
        float o = __ldg(&b2[tid]);
        #pragma unroll
        for (int k = 0; k < 16; k++)
            o += sum16[k] * __ldg(&W2[k * 32 + tid]);
        out[tid] = o;
    }
}

// ---------------------------------------------------------------------------
extern "C" void kernel_launch(void* const* d_in, const int* in_sizes, int n_in,
                              void* d_out, int out_size) {
    const float* x   = (const float*)d_in[0];
    const int*   ei  = (const int*)d_in[1];
    const float* W1  = (const float*)d_in[2];
    const float* b1  = (const float*)d_in[3];
    const float* W2  = (const float*)d_in[4];
    const float* b2  = (const float*)d_in[5];
    float*       out = (float*)d_out;

    int E = in_sizes[1] / 2;
    const int* src = ei;
    const int* dst = ei + E;

    int nb_hist = (E + 255) / 256;
    if (nb_hist > 9600) nb_hist = 9600;
    int nb_scat = (E + 511) / 512;          // 2 edges/thread

    k_hist<<<nb_hist, 256>>>(dst, E);
    k_node_prep<<<(NN + 255) / 256, 256>>>(x);
    k_scatter<<<nb_scat, 256>>>(src, dst, E);
    k_layer1<<<L1_BLOCKS, 256>>>(W1, b1);
    k_final<<<1, 256>>>(W2, b2, out);
}